// round 11
// baseline (speedup 1.0000x reference)
#include <cuda_runtime.h>
#include <math.h>
#include <stdint.h>

// Problem constants
#define FFT_N   16384            // next_pow2(L + K - 1)
#define L_IN    8192
#define K_FILT  8192
#define D_CH    256
#define B_SZ    8
#define TH      512              // threads per FFT CTA (16 warps, ~128 regs/thr: RF-full, no spills)
#define START_OFF 4095           // (K-1)//2
#define DH      (D_CH/2)         // 128 float2 per (b,l) row
#define NTASK   1024             // conv tasks: (b, channel-pair m)
#define GRID    148              // persistent conv CTAs, 1 per SM
#define FILT_CTAS 128
#define TIN_CTAS  256            // transpose CTAs fused into prep (4 tiles each)

// Padded shared-memory indexing: pad every 16 float2 (conflict-free for all pass patterns)
#define SM_IDX(a) ((a) + ((a) >> 4))
#define SM_DATA_SZ (FFT_N + (FFT_N >> 4))                        // 17408 float2

// Compact per-pass twiddle tables (contiguous, stride-1 indexed -> conflict-free)
#define TW_T1    0        // W^k,       k<1024
#define TW_T4    1024     // W^{4k},    k<1024
#define TW_T16   2048     // W^{16k},   k<64
#define TW_T64   2112     // W^{64k},   k<64
#define TW_T256  2176     // W^{256k},  k<4
#define TW_T1024 2180     // W^{1024k}, k<4
#define TW_TOT   2184

#define SMEM_BYTES ((SM_DATA_SZ + TW_TOT) * (int)sizeof(float2))  // 156736 B

// Device-global scratch (allocation-free)
__device__ __align__(16) float2 g_Hf[(size_t)D_CH * FFT_N];      // filter spectra, digit-reversed, * (1/N)
__device__ __align__(16) float2 g_ut[(size_t)NTASK * L_IN];      // packed-complex transposed input (64 MB)

__device__ __forceinline__ float2 cadd(float2 a, float2 b){ return make_float2(a.x+b.x, a.y+b.y); }
__device__ __forceinline__ float2 csub(float2 a, float2 b){ return make_float2(a.x-b.x, a.y-b.y); }
__device__ __forceinline__ float2 cmul(float2 a, float2 b){
    return make_float2(a.x*b.x - a.y*b.y, a.x*b.y + a.y*b.x);
}
__device__ __forceinline__ float2 cmulc(float2 a, float2 b){   // a * conj(b)
    return make_float2(a.x*b.x + a.y*b.y, a.y*b.x - a.x*b.y);
}
// base-4 digit reversal of a 14-bit index (7 digits)
__device__ __forceinline__ int rev4_14(int p){
    unsigned x = __brev((unsigned)p) >> 18;
    return (int)(((x & 0x1555u) << 1) | ((x >> 1) & 0x1555u));
}

// Power-of-W mapping for compact table entry s
__device__ __forceinline__ int tw_pow(int s){
    if (s < TW_T4)    return s;
    if (s < TW_T16)   return 4    * (s - TW_T4);
    if (s < TW_T64)   return 16   * (s - TW_T16);
    if (s < TW_T256)  return 64   * (s - TW_T64);
    if (s < TW_T1024) return 256  * (s - TW_T256);
    return 1024 * (s - TW_T1024);
}

// In-CTA twiddle table generation (overlaps outstanding async loads)
__device__ __forceinline__ void gen_twtab(float2* __restrict__ stw){
    const float w0 = -6.283185307179586f / (float)FFT_N;
    for (int s = threadIdx.x; s < TW_TOT; s += TH){
        float sn, cs;
        sincosf(w0 * (float)tw_pow(s), &sn, &cs);
        stw[s] = make_float2(cs, sn);
    }
}

// 8-byte async copy global -> shared (register-free)
__device__ __forceinline__ void cp_async8(void* smem_ptr, const void* gptr){
    uint32_t sa = (uint32_t)__cvta_generic_to_shared(smem_ptr);
    asm volatile("cp.async.ca.shared.global [%0], [%1], 8;\n" :: "r"(sa), "l"(gptr));
}
__device__ __forceinline__ void cp_async_wait_all(){
    asm volatile("cp.async.wait_all;\n" ::: "memory");
}

// Prefetch one conv task's input from g_ut (fully coalesced) into data[0..8191] natural slots.
__device__ __forceinline__ void prefetch_task(float2* __restrict__ data, int task){
    const float2* __restrict__ src = g_ut + ((size_t)task << 13);
    #pragma unroll
    for (int k = 0; k < 16; ++k){
        int idx = threadIdx.x + k*TH;       // 0..8191, consecutive lanes -> consecutive addresses
        cp_async8(&data[SM_IDX(idx)], &src[idx]);
    }
}

// W_N^1024 = e^{-i*pi/8}
#define CW_RE 0.9238795325112867f
#define CW_IM (-0.3826834323650898f)

// ---------------- Fused radix-16 passes (two radix-4 stages in registers) ----------------
template<int LQQ>
__device__ __forceinline__ void pass_fwd(float2* __restrict__ d,
                                         const float2* __restrict__ twW,
                                         const float2* __restrict__ twV){
    const int qq = 1 << LQQ, q = qq << 2;
    #pragma unroll
    for (int t2 = threadIdx.x; t2 < FFT_N/16; t2 += TH){
        int bb = t2 >> LQQ;
        int ii = t2 & (qq - 1);
        int base = bb*(q << 2) + ii;
        float2 x[4][4];
        #pragma unroll
        for (int t = 0; t < 4; ++t)
            #pragma unroll
            for (int j = 0; j < 4; ++j)
                x[t][j] = d[SM_IDX(base + t*q + j*qq)];
        float2 w = twW[ii];
        const float2 cw = make_float2(CW_RE, CW_IM);
        #pragma unroll
        for (int j = 0; j < 4; ++j){
            float2 t0 = cadd(x[0][j], x[2][j]), t1 = csub(x[0][j], x[2][j]);
            float2 t2c = cadd(x[1][j], x[3][j]);
            float2 u  = csub(x[1][j], x[3][j]);
            float2 t3 = make_float2(u.y, -u.x);
            float2 w2 = cmul(w, w), w3 = cmul(w2, w);
            x[0][j] = cadd(t0, t2c);
            x[1][j] = cmul(cadd(t1, t3), w);
            x[2][j] = cmul(csub(t0, t2c), w2);
            x[3][j] = cmul(csub(t1, t3), w3);
            w = cmul(w, cw);
        }
        float2 v = twV[ii];
        float2 v2 = cmul(v, v), v3 = cmul(v2, v);
        #pragma unroll
        for (int t = 0; t < 4; ++t){
            float2 t0 = cadd(x[t][0], x[t][2]), t1 = csub(x[t][0], x[t][2]);
            float2 t2c = cadd(x[t][1], x[t][3]);
            float2 u  = csub(x[t][1], x[t][3]);
            float2 t3 = make_float2(u.y, -u.x);
            x[t][0] = cadd(t0, t2c);
            x[t][1] = cmul(cadd(t1, t3), v);
            x[t][2] = cmul(csub(t0, t2c), v2);
            x[t][3] = cmul(csub(t1, t3), v3);
        }
        #pragma unroll
        for (int t = 0; t < 4; ++t)
            #pragma unroll
            for (int j = 0; j < 4; ++j)
                d[SM_IDX(base + t*q + j*qq)] = x[t][j];
    }
    __syncthreads();
}

template<int LQQ>
__device__ __forceinline__ void pass_inv(float2* __restrict__ d,
                                         const float2* __restrict__ twW,
                                         const float2* __restrict__ twV){
    const int qq = 1 << LQQ, q = qq << 2;
    #pragma unroll
    for (int t2 = threadIdx.x; t2 < FFT_N/16; t2 += TH){
        int bb = t2 >> LQQ;
        int ii = t2 & (qq - 1);
        int base = bb*(q << 2) + ii;
        float2 x[4][4];
        #pragma unroll
        for (int t = 0; t < 4; ++t)
            #pragma unroll
            for (int j = 0; j < 4; ++j)
                x[t][j] = d[SM_IDX(base + t*q + j*qq)];
        float2 v = twV[ii];
        float2 v2 = cmul(v, v), v3 = cmul(v2, v);
        #pragma unroll
        for (int t = 0; t < 4; ++t){
            float2 u1 = cmulc(x[t][1], v);
            float2 u2 = cmulc(x[t][2], v2);
            float2 u3 = cmulc(x[t][3], v3);
            float2 a  = cadd(x[t][0], u2), b = csub(x[t][0], u2);
            float2 cc = cadd(u1, u3), e = csub(u1, u3);
            float2 ie = make_float2(-e.y, e.x);
            x[t][0] = cadd(a, cc);
            x[t][1] = cadd(b, ie);
            x[t][2] = csub(a, cc);
            x[t][3] = csub(b, ie);
        }
        float2 w = twW[ii];
        const float2 cw = make_float2(CW_RE, CW_IM);
        #pragma unroll
        for (int j = 0; j < 4; ++j){
            float2 w2 = cmul(w, w), w3 = cmul(w2, w);
            float2 u1 = cmulc(x[1][j], w);
            float2 u2 = cmulc(x[2][j], w2);
            float2 u3 = cmulc(x[3][j], w3);
            float2 a  = cadd(x[0][j], u2), b = csub(x[0][j], u2);
            float2 cc = cadd(u1, u3), e = csub(u1, u3);
            float2 ie = make_float2(-e.y, e.x);
            x[0][j] = cadd(a, cc);
            x[1][j] = cadd(b, ie);
            x[2][j] = csub(a, cc);
            x[3][j] = csub(b, ie);
            w = cmul(w, cw);
        }
        #pragma unroll
        for (int t = 0; t < 4; ++t)
            #pragma unroll
            for (int j = 0; j < 4; ++j)
                d[SM_IDX(base + t*q + j*qq)] = x[t][j];
    }
    __syncthreads();
}

// First forward pass (stages 0,1). x[0..1][*] provided, x[2..3] implicit zeros.
__device__ __forceinline__ void pass01_core(float2 (&x)[4][4], int ii,
                                            float2* __restrict__ d,
                                            const float2* __restrict__ twW,
                                            const float2* __restrict__ twV){
    float2 w = twW[ii];
    const float2 cw = make_float2(CW_RE, CW_IM);
    #pragma unroll
    for (int j = 0; j < 4; ++j){
        float2 t0 = cadd(x[0][j], x[2][j]), t1 = csub(x[0][j], x[2][j]);
        float2 t2c = cadd(x[1][j], x[3][j]);
        float2 u  = csub(x[1][j], x[3][j]);
        float2 t3 = make_float2(u.y, -u.x);
        float2 w2 = cmul(w, w), w3 = cmul(w2, w);
        x[0][j] = cadd(t0, t2c);
        x[1][j] = cmul(cadd(t1, t3), w);
        x[2][j] = cmul(csub(t0, t2c), w2);
        x[3][j] = cmul(csub(t1, t3), w3);
        w = cmul(w, cw);
    }
    float2 v = twV[ii];
    float2 v2 = cmul(v, v), v3 = cmul(v2, v);
    #pragma unroll
    for (int t = 0; t < 4; ++t){
        float2 t0 = cadd(x[t][0], x[t][2]), t1 = csub(x[t][0], x[t][2]);
        float2 t2c = cadd(x[t][1], x[t][3]);
        float2 u  = csub(x[t][1], x[t][3]);
        float2 t3 = make_float2(u.y, -u.x);
        x[t][0] = cadd(t0, t2c);
        x[t][1] = cmul(cadd(t1, t3), v);
        x[t][2] = cmul(csub(t0, t2c), v2);
        x[t][3] = cmul(csub(t1, t3), v3);
    }
    #pragma unroll
    for (int t = 0; t < 4; ++t)
        #pragma unroll
        for (int j = 0; j < 4; ++j)
            d[SM_IDX(t*4096 + j*1024 + ii)] = x[t][j];
}

// Last inverse pass (stages 1,0): compute one ii-slice into registers.
__device__ __forceinline__ void pass10_compute(const float2* __restrict__ d,
                                               const float2* __restrict__ twW,
                                               const float2* __restrict__ twV,
                                               int ii, float2 (&x)[4][4]){
    #pragma unroll
    for (int t = 0; t < 4; ++t)
        #pragma unroll
        for (int j = 0; j < 4; ++j)
            x[t][j] = d[SM_IDX(t*4096 + j*1024 + ii)];
    float2 v = twV[ii];
    float2 v2 = cmul(v, v), v3 = cmul(v2, v);
    #pragma unroll
    for (int t = 0; t < 4; ++t){
        float2 u1 = cmulc(x[t][1], v);
        float2 u2 = cmulc(x[t][2], v2);
        float2 u3 = cmulc(x[t][3], v3);
        float2 a  = cadd(x[t][0], u2), b = csub(x[t][0], u2);
        float2 cc = cadd(u1, u3), e = csub(u1, u3);
        float2 ie = make_float2(-e.y, e.x);
        x[t][0] = cadd(a, cc);
        x[t][1] = cadd(b, ie);
        x[t][2] = csub(a, cc);
        x[t][3] = csub(b, ie);
    }
    float2 w = twW[ii];
    const float2 cw = make_float2(CW_RE, CW_IM);
    #pragma unroll
    for (int j = 0; j < 4; ++j){
        float2 w2 = cmul(w, w), w3 = cmul(w2, w);
        float2 u1 = cmulc(x[1][j], w);
        float2 u2 = cmulc(x[2][j], w2);
        float2 u3 = cmulc(x[3][j], w3);
        float2 a  = cadd(x[0][j], u2), b = csub(x[0][j], u2);
        float2 cc = cadd(u1, u3), e = csub(u1, u3);
        float2 ie = make_float2(-e.y, e.x);
        x[0][j] = cadd(a, cc);
        x[1][j] = cadd(b, ie);
        x[2][j] = csub(a, cc);
        x[3][j] = csub(b, ie);
        w = cmul(w, cw);
    }
}

__device__ __forceinline__ void pass10_store(float2* __restrict__ dst, int ii, float2 (&x)[4][4]){
    #pragma unroll
    for (int t = 0; t < 4; ++t)
        #pragma unroll
        for (int j = 0; j < 4; ++j){
            int p = t*4096 + j*1024 + ii;
            int l = p - START_OFF;
            if (l >= 0 && l < L_IN)
                dst[(size_t)l * DH] = x[t][j];
        }
}

// ---------------- Kernels ----------------
// prep_kernel: CTAs [0,128): filter spectra (packed real-pair FFT + conj-symmetry unpack).
//              CTAs [128,384): input transpose u(B,L,D) -> g_ut[task][l] packed complex.
// The two populations use disjoint pipes (fma/smem vs DRAM) and overlap.
__global__ __launch_bounds__(TH, 1) void prep_kernel(const float* __restrict__ h,
                                                     const float* __restrict__ u){
    extern __shared__ float2 sm[];
    if (blockIdx.x >= FILT_CTAS){
        // ---- transpose path: 4 tiles of (64 l) x (128 channel-pairs) each ----
        float* tileX = (float*)sm;                 // [64][129] floats
        float* tileY = tileX + 64*129;
        const int c2 = blockIdx.x - FILT_CTAS;
        for (int tt = 0; tt < 4; ++tt){
            const int tl = c2*4 + tt;              // 0..1023
            const int b  = tl >> 7;
            const int l0 = (tl & 127) << 6;
            const float2* __restrict__ u2 = (const float2*)u + ((size_t)b * L_IN + l0) * DH;
            if (tt) __syncthreads();               // previous tile's reads complete
            #pragma unroll
            for (int k = 0; k < 16; ++k){
                int idx = threadIdx.x + k*TH;      // 0..8191
                int dl = idx >> 7, mc = idx & 127;
                float2 v = u2[(size_t)dl * DH + mc];   // coalesced 128B/warp
                tileX[dl*129 + mc] = v.x;              // lanes stride-1: conflict-free
                tileY[dl*129 + mc] = v.y;
            }
            __syncthreads();
            #pragma unroll
            for (int k = 0; k < 16; ++k){
                int idx2 = threadIdx.x + k*TH;
                int m = idx2 >> 6, dl = idx2 & 63;
                float2 v = make_float2(tileX[dl*129 + m], tileY[dl*129 + m]); // stride 129 = 1 mod 32
                g_ut[(((size_t)(b*128 + m)) << 13) + l0 + dl] = v;            // 256B coalesced runs
            }
        }
        return;
    }

    // ---- filter path ----
    float2* data = sm;
    float2* stw  = sm + SM_DATA_SZ;
    const int g = blockIdx.x;
    const float* __restrict__ h0 = h + (size_t)(2*g) * K_FILT;
    const float* __restrict__ h1 = h + (size_t)(2*g+1) * K_FILT;

    gen_twtab(stw);
    __syncthreads();

    #pragma unroll
    for (int r = 0; r < 2; ++r){
        int ii = threadIdx.x + r*TH;
        float2 x[4][4];
        #pragma unroll
        for (int t = 0; t < 4; ++t)
            #pragma unroll
            for (int j = 0; j < 4; ++j){
                if (t < 2){
                    int idx = t*4096 + j*1024 + ii;
                    x[t][j] = make_float2(h0[idx], h1[idx]);
                } else x[t][j] = make_float2(0.0f, 0.0f);
            }
        pass01_core(x, ii, data, stw + TW_T1, stw + TW_T4);
    }
    __syncthreads();
    pass_fwd<6>(data, stw + TW_T16,  stw + TW_T64);    // stages 2,3
    pass_fwd<2>(data, stw + TW_T256, stw + TW_T1024);  // stages 4,5

    // stage 6 (twiddle-free), in smem
    #pragma unroll
    for (int k = threadIdx.x; k < FFT_N/4; k += TH){
        int base = 4*k;
        float2 x0 = data[SM_IDX(base)],   x1 = data[SM_IDX(base+1)];
        float2 x2 = data[SM_IDX(base+2)], x3 = data[SM_IDX(base+3)];
        float2 t0 = cadd(x0, x2), t1 = csub(x0, x2), t2 = cadd(x1, x3);
        float2 u5  = csub(x1, x3);
        float2 t3 = make_float2(u5.y, -u5.x);
        data[SM_IDX(base)]   = cadd(t0, t2);
        data[SM_IDX(base+1)] = cadd(t1, t3);
        data[SM_IDX(base+2)] = csub(t0, t2);
        data[SM_IDX(base+3)] = csub(t1, t3);
    }
    __syncthreads();

    // Unpack: position p holds freq k=rev4(p); mirror at pm=rev4((N-k)&(N-1)).
    const float sc = 0.5f / (float)FFT_N;
    float2* H0 = g_Hf + (size_t)(2*g)   * FFT_N;
    float2* H1 = g_Hf + (size_t)(2*g+1) * FFT_N;
    #pragma unroll
    for (int p = threadIdx.x; p < FFT_N; p += TH){
        int k  = rev4_14(p);
        int pm = rev4_14((FFT_N - k) & (FFT_N - 1));
        float2 Zp = data[SM_IDX(p)];
        float2 Zm = data[SM_IDX(pm)];
        H0[p] = make_float2((Zp.x + Zm.x)*sc, (Zp.y - Zm.y)*sc);
        H1[p] = make_float2((Zp.y + Zm.y)*sc, (Zm.x - Zp.x)*sc);
    }
}

// Persistent conv: 148 CTAs loop over 1024 tasks. Task (b,m): channels 2m,2m+1 of
// batch b, filter f = b*32 + m/4. Input prefetched coalesced from g_ut via cp.async
// during the previous task's store phase.
__global__ __launch_bounds__(TH, 1) void conv_kernel(float* __restrict__ out){
    extern __shared__ float2 sm[];
    float2* data = sm;
    float2* stw  = sm + SM_DATA_SZ;

    int task = blockIdx.x;
    if (task < NTASK) prefetch_task(data, task);   // overlaps twiddle generation
    gen_twtab(stw);

    for (; task < NTASK; task += GRID){
        cp_async_wait_all();
        __syncthreads();

        const int b = task >> 7;
        const int m = task & 127;
        const int f = b * 32 + (m >> 2);

        // pass01 from prefetched smem input (top half implicit zeros)
        #pragma unroll
        for (int r = 0; r < 2; ++r){
            int ii = threadIdx.x + r*TH;
            float2 x[4][4];
            #pragma unroll
            for (int t = 0; t < 4; ++t)
                #pragma unroll
                for (int j = 0; j < 4; ++j){
                    if (t < 2) x[t][j] = data[SM_IDX(t*4096 + j*1024 + ii)];
                    else       x[t][j] = make_float2(0.0f, 0.0f);
                }
            pass01_core(x, ii, data, stw + TW_T1, stw + TW_T4);
        }
        __syncthreads();

        pass_fwd<6>(data, stw + TW_T16,  stw + TW_T64);
        pass_fwd<2>(data, stw + TW_T256, stw + TW_T1024);

        // stage 6 fwd + pointwise * H + stage 6 inv, in registers
        const float2* __restrict__ Hrow = g_Hf + (size_t)f * FFT_N;
        #pragma unroll
        for (int k = threadIdx.x; k < FFT_N/4; k += TH){
            int base = 4*k;
            float2 x0 = data[SM_IDX(base)],   x1 = data[SM_IDX(base+1)];
            float2 x2 = data[SM_IDX(base+2)], x3 = data[SM_IDX(base+3)];
            float2 t0 = cadd(x0, x2), t1 = csub(x0, x2), t2 = cadd(x1, x3);
            float2 u2v = csub(x1, x3);
            float2 t3 = make_float2(u2v.y, -u2v.x);
            float2 y0 = cadd(t0, t2), y1 = cadd(t1, t3), y2 = csub(t0, t2), y3 = csub(t1, t3);
            float4 hA = *reinterpret_cast<const float4*>(Hrow + base);
            float4 hB = *reinterpret_cast<const float4*>(Hrow + base + 2);
            y0 = cmul(y0, make_float2(hA.x, hA.y));
            y1 = cmul(y1, make_float2(hA.z, hA.w));
            y2 = cmul(y2, make_float2(hB.x, hB.y));
            y3 = cmul(y3, make_float2(hB.z, hB.w));
            float2 a  = cadd(y0, y2), bb = csub(y0, y2);
            float2 cc = cadd(y1, y3), e  = csub(y1, y3);
            float2 ie = make_float2(-e.y, e.x);
            data[SM_IDX(base)]   = cadd(a, cc);
            data[SM_IDX(base+1)] = cadd(bb, ie);
            data[SM_IDX(base+2)] = csub(a, cc);
            data[SM_IDX(base+3)] = csub(bb, ie);
        }
        __syncthreads();

        pass_inv<2>(data, stw + TW_T256, stw + TW_T1024);  // stages 5,4
        pass_inv<6>(data, stw + TW_T16,  stw + TW_T64);    // stages 3,2

        // Final pass (stages 1,0) + windowed strided store; prefetch next task during stores.
        float2* dst = (float2*)out + (size_t)b * L_IN * DH + m;

        {   // slice r=0: compute + store immediately
            float2 y[4][4];
            pass10_compute(data, stw + TW_T1, stw + TW_T4, threadIdx.x, y);
            pass10_store(dst, threadIdx.x, y);
        }
        {   // slice r=1: compute, barrier (smem reads done), prefetch, then store
            float2 y[4][4];
            pass10_compute(data, stw + TW_T1, stw + TW_T4, threadIdx.x + TH, y);
            __syncthreads();                       // all smem reads of this task complete
            int nt = task + GRID;
            if (nt < NTASK) prefetch_task(data, nt);   // coalesced cp.async into data[0..8191]
            pass10_store(dst, threadIdx.x + TH, y);
        }
    }
}

extern "C" void kernel_launch(void* const* d_in, const int* in_sizes, int n_in,
                              void* d_out, int out_size){
    const float* u = (const float*)d_in[0];
    const float* h = (const float*)d_in[1];
    float* out     = (float*)d_out;

    cudaFuncSetAttribute(prep_kernel, cudaFuncAttributeMaxDynamicSharedMemorySize, SMEM_BYTES);
    cudaFuncSetAttribute(conv_kernel, cudaFuncAttributeMaxDynamicSharedMemorySize, SMEM_BYTES);

    prep_kernel<<<FILT_CTAS + TIN_CTAS, TH, SMEM_BYTES>>>(h, u);
    conv_kernel<<<GRID, TH, SMEM_BYTES>>>(out);
}

// round 12
// speedup vs baseline: 1.4951x; 1.4951x over previous
#include <cuda_runtime.h>
#include <math.h>
#include <stdint.h>

// Problem constants
#define FFT_N   16384            // next_pow2(L + K - 1)
#define L_IN    8192
#define K_FILT  8192
#define D_CH    256
#define B_SZ    8
#define TH      512              // threads per FFT CTA (16 warps, ~128 regs/thr: RF-full, no spills)
#define START_OFF 4095           // (K-1)//2
#define DH      (D_CH/2)         // 128 float2 per (b,l) row
#define NTASK   1024             // conv tasks: (b, channel-pair m)
#define GRID    148              // persistent conv CTAs, 1 per SM

// Padded shared-memory indexing: pad every 16 float2 (conflict-free for all pass patterns)
#define SM_IDX(a) ((a) + ((a) >> 4))
#define SM_DATA_SZ (FFT_N + (FFT_N >> 4))                        // 17408 float2

// Compact per-pass twiddle tables (contiguous, stride-1 indexed -> conflict-free)
#define TW_T1    0        // W^k,       k<1024
#define TW_T4    1024     // W^{4k},    k<1024
#define TW_T16   2048     // W^{16k},   k<64
#define TW_T64   2112     // W^{64k},   k<64
#define TW_T256  2176     // W^{256k},  k<4
#define TW_T1024 2180     // W^{1024k}, k<4
#define TW_TOT   2184

#define SMEM_BYTES ((SM_DATA_SZ + TW_TOT) * (int)sizeof(float2))  // 156736 B

// Filter spectra scratch (device global; allocation-free)
__device__ __align__(16) float2 g_Hf[(size_t)D_CH * FFT_N];      // digit-reversed, * (1/N)

__device__ __forceinline__ float2 cadd(float2 a, float2 b){ return make_float2(a.x+b.x, a.y+b.y); }
__device__ __forceinline__ float2 csub(float2 a, float2 b){ return make_float2(a.x-b.x, a.y-b.y); }
__device__ __forceinline__ float2 cmul(float2 a, float2 b){
    return make_float2(a.x*b.x - a.y*b.y, a.x*b.y + a.y*b.x);
}
__device__ __forceinline__ float2 cmulc(float2 a, float2 b){   // a * conj(b)
    return make_float2(a.x*b.x + a.y*b.y, a.y*b.x - a.x*b.y);
}
// base-4 digit reversal of a 14-bit index (7 digits)
__device__ __forceinline__ int rev4_14(int p){
    unsigned x = __brev((unsigned)p) >> 18;
    return (int)(((x & 0x1555u) << 1) | ((x >> 1) & 0x1555u));
}

// Power-of-W mapping for compact table entry s
__device__ __forceinline__ int tw_pow(int s){
    if (s < TW_T4)    return s;
    if (s < TW_T16)   return 4    * (s - TW_T4);
    if (s < TW_T64)   return 16   * (s - TW_T16);
    if (s < TW_T256)  return 64   * (s - TW_T64);
    if (s < TW_T1024) return 256  * (s - TW_T256);
    return 1024 * (s - TW_T1024);
}

// In-CTA twiddle table generation
__device__ __forceinline__ void gen_twtab(float2* __restrict__ stw){
    const float w0 = -6.283185307179586f / (float)FFT_N;
    for (int s = threadIdx.x; s < TW_TOT; s += TH){
        float sn, cs;
        sincosf(w0 * (float)tw_pow(s), &sn, &cs);
        stw[s] = make_float2(cs, sn);
    }
}

// W_N^1024 = e^{-i*pi/8}
#define CW_RE 0.9238795325112867f
#define CW_IM (-0.3826834323650898f)

// ---------------- Fused radix-16 passes (two radix-4 stages in registers) ----------------
template<int LQQ>
__device__ __forceinline__ void pass_fwd(float2* __restrict__ d,
                                         const float2* __restrict__ twW,
                                         const float2* __restrict__ twV){
    const int qq = 1 << LQQ, q = qq << 2;
    #pragma unroll
    for (int t2 = threadIdx.x; t2 < FFT_N/16; t2 += TH){
        int bb = t2 >> LQQ;
        int ii = t2 & (qq - 1);
        int base = bb*(q << 2) + ii;
        float2 x[4][4];
        #pragma unroll
        for (int t = 0; t < 4; ++t)
            #pragma unroll
            for (int j = 0; j < 4; ++j)
                x[t][j] = d[SM_IDX(base + t*q + j*qq)];
        float2 w = twW[ii];
        const float2 cw = make_float2(CW_RE, CW_IM);
        #pragma unroll
        for (int j = 0; j < 4; ++j){
            float2 t0 = cadd(x[0][j], x[2][j]), t1 = csub(x[0][j], x[2][j]);
            float2 t2c = cadd(x[1][j], x[3][j]);
            float2 u  = csub(x[1][j], x[3][j]);
            float2 t3 = make_float2(u.y, -u.x);
            float2 w2 = cmul(w, w), w3 = cmul(w2, w);
            x[0][j] = cadd(t0, t2c);
            x[1][j] = cmul(cadd(t1, t3), w);
            x[2][j] = cmul(csub(t0, t2c), w2);
            x[3][j] = cmul(csub(t1, t3), w3);
            w = cmul(w, cw);
        }
        float2 v = twV[ii];
        float2 v2 = cmul(v, v), v3 = cmul(v2, v);
        #pragma unroll
        for (int t = 0; t < 4; ++t){
            float2 t0 = cadd(x[t][0], x[t][2]), t1 = csub(x[t][0], x[t][2]);
            float2 t2c = cadd(x[t][1], x[t][3]);
            float2 u  = csub(x[t][1], x[t][3]);
            float2 t3 = make_float2(u.y, -u.x);
            x[t][0] = cadd(t0, t2c);
            x[t][1] = cmul(cadd(t1, t3), v);
            x[t][2] = cmul(csub(t0, t2c), v2);
            x[t][3] = cmul(csub(t1, t3), v3);
        }
        #pragma unroll
        for (int t = 0; t < 4; ++t)
            #pragma unroll
            for (int j = 0; j < 4; ++j)
                d[SM_IDX(base + t*q + j*qq)] = x[t][j];
    }
    __syncthreads();
}

template<int LQQ>
__device__ __forceinline__ void pass_inv(float2* __restrict__ d,
                                         const float2* __restrict__ twW,
                                         const float2* __restrict__ twV){
    const int qq = 1 << LQQ, q = qq << 2;
    #pragma unroll
    for (int t2 = threadIdx.x; t2 < FFT_N/16; t2 += TH){
        int bb = t2 >> LQQ;
        int ii = t2 & (qq - 1);
        int base = bb*(q << 2) + ii;
        float2 x[4][4];
        #pragma unroll
        for (int t = 0; t < 4; ++t)
            #pragma unroll
            for (int j = 0; j < 4; ++j)
                x[t][j] = d[SM_IDX(base + t*q + j*qq)];
        float2 v = twV[ii];
        float2 v2 = cmul(v, v), v3 = cmul(v2, v);
        #pragma unroll
        for (int t = 0; t < 4; ++t){
            float2 u1 = cmulc(x[t][1], v);
            float2 u2 = cmulc(x[t][2], v2);
            float2 u3 = cmulc(x[t][3], v3);
            float2 a  = cadd(x[t][0], u2), b = csub(x[t][0], u2);
            float2 cc = cadd(u1, u3), e = csub(u1, u3);
            float2 ie = make_float2(-e.y, e.x);
            x[t][0] = cadd(a, cc);
            x[t][1] = cadd(b, ie);
            x[t][2] = csub(a, cc);
            x[t][3] = csub(b, ie);
        }
        float2 w = twW[ii];
        const float2 cw = make_float2(CW_RE, CW_IM);
        #pragma unroll
        for (int j = 0; j < 4; ++j){
            float2 w2 = cmul(w, w), w3 = cmul(w2, w);
            float2 u1 = cmulc(x[1][j], w);
            float2 u2 = cmulc(x[2][j], w2);
            float2 u3 = cmulc(x[3][j], w3);
            float2 a  = cadd(x[0][j], u2), b = csub(x[0][j], u2);
            float2 cc = cadd(u1, u3), e = csub(u1, u3);
            float2 ie = make_float2(-e.y, e.x);
            x[0][j] = cadd(a, cc);
            x[1][j] = cadd(b, ie);
            x[2][j] = csub(a, cc);
            x[3][j] = csub(b, ie);
            w = cmul(w, cw);
        }
        #pragma unroll
        for (int t = 0; t < 4; ++t)
            #pragma unroll
            for (int j = 0; j < 4; ++j)
                d[SM_IDX(base + t*q + j*qq)] = x[t][j];
    }
    __syncthreads();
}

// First forward pass (stages 0,1). x[0..1][*] provided, x[2..3] implicit zeros.
__device__ __forceinline__ void pass01_core(float2 (&x)[4][4], int ii,
                                            float2* __restrict__ d,
                                            const float2* __restrict__ twW,
                                            const float2* __restrict__ twV){
    float2 w = twW[ii];
    const float2 cw = make_float2(CW_RE, CW_IM);
    #pragma unroll
    for (int j = 0; j < 4; ++j){
        float2 t0 = cadd(x[0][j], x[2][j]), t1 = csub(x[0][j], x[2][j]);
        float2 t2c = cadd(x[1][j], x[3][j]);
        float2 u  = csub(x[1][j], x[3][j]);
        float2 t3 = make_float2(u.y, -u.x);
        float2 w2 = cmul(w, w), w3 = cmul(w2, w);
        x[0][j] = cadd(t0, t2c);
        x[1][j] = cmul(cadd(t1, t3), w);
        x[2][j] = cmul(csub(t0, t2c), w2);
        x[3][j] = cmul(csub(t1, t3), w3);
        w = cmul(w, cw);
    }
    float2 v = twV[ii];
    float2 v2 = cmul(v, v), v3 = cmul(v2, v);
    #pragma unroll
    for (int t = 0; t < 4; ++t){
        float2 t0 = cadd(x[t][0], x[t][2]), t1 = csub(x[t][0], x[t][2]);
        float2 t2c = cadd(x[t][1], x[t][3]);
        float2 u  = csub(x[t][1], x[t][3]);
        float2 t3 = make_float2(u.y, -u.x);
        x[t][0] = cadd(t0, t2c);
        x[t][1] = cmul(cadd(t1, t3), v);
        x[t][2] = cmul(csub(t0, t2c), v2);
        x[t][3] = cmul(csub(t1, t3), v3);
    }
    #pragma unroll
    for (int t = 0; t < 4; ++t)
        #pragma unroll
        for (int j = 0; j < 4; ++j)
            d[SM_IDX(t*4096 + j*1024 + ii)] = x[t][j];
}

// Last inverse pass (stages 1,0): compute one ii-slice into registers.
__device__ __forceinline__ void pass10_compute(const float2* __restrict__ d,
                                               const float2* __restrict__ twW,
                                               const float2* __restrict__ twV,
                                               int ii, float2 (&x)[4][4]){
    #pragma unroll
    for (int t = 0; t < 4; ++t)
        #pragma unroll
        for (int j = 0; j < 4; ++j)
            x[t][j] = d[SM_IDX(t*4096 + j*1024 + ii)];
    float2 v = twV[ii];
    float2 v2 = cmul(v, v), v3 = cmul(v2, v);
    #pragma unroll
    for (int t = 0; t < 4; ++t){
        float2 u1 = cmulc(x[t][1], v);
        float2 u2 = cmulc(x[t][2], v2);
        float2 u3 = cmulc(x[t][3], v3);
        float2 a  = cadd(x[t][0], u2), b = csub(x[t][0], u2);
        float2 cc = cadd(u1, u3), e = csub(u1, u3);
        float2 ie = make_float2(-e.y, e.x);
        x[t][0] = cadd(a, cc);
        x[t][1] = cadd(b, ie);
        x[t][2] = csub(a, cc);
        x[t][3] = csub(b, ie);
    }
    float2 w = twW[ii];
    const float2 cw = make_float2(CW_RE, CW_IM);
    #pragma unroll
    for (int j = 0; j < 4; ++j){
        float2 w2 = cmul(w, w), w3 = cmul(w2, w);
        float2 u1 = cmulc(x[1][j], w);
        float2 u2 = cmulc(x[2][j], w2);
        float2 u3 = cmulc(x[3][j], w3);
        float2 a  = cadd(x[0][j], u2), b = csub(x[0][j], u2);
        float2 cc = cadd(u1, u3), e = csub(u1, u3);
        float2 ie = make_float2(-e.y, e.x);
        x[0][j] = cadd(a, cc);
        x[1][j] = cadd(b, ie);
        x[2][j] = csub(a, cc);
        x[3][j] = csub(b, ie);
        w = cmul(w, cw);
    }
}

__device__ __forceinline__ void pass10_store(float2* __restrict__ dst, int ii, float2 (&x)[4][4]){
    #pragma unroll
    for (int t = 0; t < 4; ++t)
        #pragma unroll
        for (int j = 0; j < 4; ++j){
            int p = t*4096 + j*1024 + ii;
            int l = p - START_OFF;
            if (l >= 0 && l < L_IN)
                dst[(size_t)l * DH] = x[t][j];
        }
}

// ---------------- Kernels ----------------
// Filter spectra: 128 CTAs, pack filters (2g, 2g+1) into one complex FFT,
// unpack via conjugate symmetry in digit-reversed position space.
__global__ __launch_bounds__(TH, 1) void filt_kernel(const float* __restrict__ h){
    extern __shared__ float2 sm[];
    float2* data = sm;
    float2* stw  = sm + SM_DATA_SZ;
    const int g = blockIdx.x;
    const float* __restrict__ h0 = h + (size_t)(2*g) * K_FILT;
    const float* __restrict__ h1 = h + (size_t)(2*g+1) * K_FILT;

    gen_twtab(stw);
    __syncthreads();

    #pragma unroll
    for (int r = 0; r < 2; ++r){
        int ii = threadIdx.x + r*TH;
        float2 x[4][4];
        #pragma unroll
        for (int t = 0; t < 4; ++t)
            #pragma unroll
            for (int j = 0; j < 4; ++j){
                if (t < 2){
                    int idx = t*4096 + j*1024 + ii;
                    x[t][j] = make_float2(h0[idx], h1[idx]);
                } else x[t][j] = make_float2(0.0f, 0.0f);
            }
        pass01_core(x, ii, data, stw + TW_T1, stw + TW_T4);
    }
    __syncthreads();
    pass_fwd<6>(data, stw + TW_T16,  stw + TW_T64);    // stages 2,3
    pass_fwd<2>(data, stw + TW_T256, stw + TW_T1024);  // stages 4,5

    // stage 6 (twiddle-free), in smem
    #pragma unroll
    for (int k = threadIdx.x; k < FFT_N/4; k += TH){
        int base = 4*k;
        float2 x0 = data[SM_IDX(base)],   x1 = data[SM_IDX(base+1)];
        float2 x2 = data[SM_IDX(base+2)], x3 = data[SM_IDX(base+3)];
        float2 t0 = cadd(x0, x2), t1 = csub(x0, x2), t2 = cadd(x1, x3);
        float2 u  = csub(x1, x3);
        float2 t3 = make_float2(u.y, -u.x);
        data[SM_IDX(base)]   = cadd(t0, t2);
        data[SM_IDX(base+1)] = cadd(t1, t3);
        data[SM_IDX(base+2)] = csub(t0, t2);
        data[SM_IDX(base+3)] = csub(t1, t3);
    }
    __syncthreads();

    // Unpack: position p holds freq k=rev4(p); mirror at pm=rev4((N-k)&(N-1)).
    const float sc = 0.5f / (float)FFT_N;
    float2* H0 = g_Hf + (size_t)(2*g)   * FFT_N;
    float2* H1 = g_Hf + (size_t)(2*g+1) * FFT_N;
    #pragma unroll
    for (int p = threadIdx.x; p < FFT_N; p += TH){
        int k  = rev4_14(p);
        int pm = rev4_14((FFT_N - k) & (FFT_N - 1));
        float2 Zp = data[SM_IDX(p)];
        float2 Zm = data[SM_IDX(pm)];
        H0[p] = make_float2((Zp.x + Zm.x)*sc, (Zp.y - Zm.y)*sc);
        H1[p] = make_float2((Zp.y + Zm.y)*sc, (Zm.x - Zp.x)*sc);
    }
}

// Persistent conv: 148 CTAs loop over 1024 tasks. Task (b,m): channels 2m,2m+1 of
// batch b, filter f = b*32 + m/4. Direct strided LDG input (L2 line-sharing across
// adjacent-m CTAs makes these mostly L2-warm); loads issued before the smem-reuse
// barrier so latency overlaps barrier drain + slice-0 compute.
__global__ __launch_bounds__(TH, 1) void conv_kernel(const float* __restrict__ u,
                                                     float* __restrict__ out){
    extern __shared__ float2 sm[];
    float2* data = sm;
    float2* stw  = sm + SM_DATA_SZ;

    gen_twtab(stw);

    for (int task = blockIdx.x; task < NTASK; task += GRID){
        const int b = task >> 7;
        const int m = task & 127;
        const int f = b * 32 + (m >> 2);
        const float2* __restrict__ src = (const float2*)u + (size_t)b * L_IN * DH + m;

        // Issue all 16 strided loads (both slices) into registers up front.
        float2 xa[2][4], xb[2][4];
        #pragma unroll
        for (int t = 0; t < 2; ++t)
            #pragma unroll
            for (int j = 0; j < 4; ++j)
                xa[t][j] = src[(size_t)(t*4096 + j*1024 + threadIdx.x) * DH];
        #pragma unroll
        for (int t = 0; t < 2; ++t)
            #pragma unroll
            for (int j = 0; j < 4; ++j)
                xb[t][j] = src[(size_t)(t*4096 + j*1024 + threadIdx.x + TH) * DH];

        __syncthreads();   // previous task's pass10 smem reads complete (also tw table on iter 0)

        {   // slice 0
            float2 x[4][4];
            #pragma unroll
            for (int t = 0; t < 4; ++t)
                #pragma unroll
                for (int j = 0; j < 4; ++j)
                    x[t][j] = (t < 2) ? xa[t][j] : make_float2(0.0f, 0.0f);
            pass01_core(x, threadIdx.x, data, stw + TW_T1, stw + TW_T4);
        }
        {   // slice 1
            float2 x[4][4];
            #pragma unroll
            for (int t = 0; t < 4; ++t)
                #pragma unroll
                for (int j = 0; j < 4; ++j)
                    x[t][j] = (t < 2) ? xb[t][j] : make_float2(0.0f, 0.0f);
            pass01_core(x, threadIdx.x + TH, data, stw + TW_T1, stw + TW_T4);
        }
        __syncthreads();

        pass_fwd<6>(data, stw + TW_T16,  stw + TW_T64);
        pass_fwd<2>(data, stw + TW_T256, stw + TW_T1024);

        // stage 6 fwd + pointwise * H + stage 6 inv, in registers
        const float2* __restrict__ Hrow = g_Hf + (size_t)f * FFT_N;
        #pragma unroll
        for (int k = threadIdx.x; k < FFT_N/4; k += TH){
            int base = 4*k;
            float2 x0 = data[SM_IDX(base)],   x1 = data[SM_IDX(base+1)];
            float2 x2 = data[SM_IDX(base+2)], x3 = data[SM_IDX(base+3)];
            float2 t0 = cadd(x0, x2), t1 = csub(x0, x2), t2 = cadd(x1, x3);
            float2 u2v = csub(x1, x3);
            float2 t3 = make_float2(u2v.y, -u2v.x);
            float2 y0 = cadd(t0, t2), y1 = cadd(t1, t3), y2 = csub(t0, t2), y3 = csub(t1, t3);
            float4 hA = *reinterpret_cast<const float4*>(Hrow + base);
            float4 hB = *reinterpret_cast<const float4*>(Hrow + base + 2);
            y0 = cmul(y0, make_float2(hA.x, hA.y));
            y1 = cmul(y1, make_float2(hA.z, hA.w));
            y2 = cmul(y2, make_float2(hB.x, hB.y));
            y3 = cmul(y3, make_float2(hB.z, hB.w));
            float2 a  = cadd(y0, y2), bb = csub(y0, y2);
            float2 cc = cadd(y1, y3), e  = csub(y1, y3);
            float2 ie = make_float2(-e.y, e.x);
            data[SM_IDX(base)]   = cadd(a, cc);
            data[SM_IDX(base+1)] = cadd(bb, ie);
            data[SM_IDX(base+2)] = csub(a, cc);
            data[SM_IDX(base+3)] = csub(bb, ie);
        }
        __syncthreads();

        pass_inv<2>(data, stw + TW_T256, stw + TW_T1024);  // stages 5,4
        pass_inv<6>(data, stw + TW_T16,  stw + TW_T64);    // stages 3,2

        // Final pass (stages 1,0) + windowed strided store (fire-and-forget STG;
        // adjacent-m CTAs' stores merge per 32B sector in L2).
        float2* dst = (float2*)out + (size_t)b * L_IN * DH + m;
        {
            float2 y[4][4];
            pass10_compute(data, stw + TW_T1, stw + TW_T4, threadIdx.x, y);
            pass10_store(dst, threadIdx.x, y);
        }
        {
            float2 y[4][4];
            pass10_compute(data, stw + TW_T1, stw + TW_T4, threadIdx.x + TH, y);
            pass10_store(dst, threadIdx.x + TH, y);
        }
    }
}

extern "C" void kernel_launch(void* const* d_in, const int* in_sizes, int n_in,
                              void* d_out, int out_size){
    const float* u = (const float*)d_in[0];
    const float* h = (const float*)d_in[1];
    float* out     = (float*)d_out;

    cudaFuncSetAttribute(filt_kernel, cudaFuncAttributeMaxDynamicSharedMemorySize, SMEM_BYTES);
    cudaFuncSetAttribute(conv_kernel, cudaFuncAttributeMaxDynamicSharedMemorySize, SMEM_BYTES);

    filt_kernel<<<D_CH/2, TH, SMEM_BYTES>>>(h);
    conv_kernel<<<GRID, TH, SMEM_BYTES>>>(u, out);
}